// round 15
// baseline (speedup 1.0000x reference)
#include <cuda_runtime.h>
#include <math.h>
#include <stdint.h>

// ---------------- problem constants ----------------
#define Bn   2
#define Sn   2048
#define En   1024
#define Hn   1344
#define H2n  2688
#define NHn  4
#define DHn  336
#define DH4  84           // DHn/4
#define NPH  (Hn/4)       // 336 projection heads
#define TOT  (Bn*Sn)      // 4096 rows

// attention tiling (tensor-core version)
#define TQ   64
#define TK   64
#define SKS  340          // u32 row stride for Q/K/V tf32 tiles (340%32=20 -> conflict-free)
#define WS   68           // u32 row stride for W tile (68%32=4 -> conflict-free A-frags)
#define NQT  (Sn/TQ)      // 32

// smem layout (u32 units) — R11 layout
#define USM_Q   0
#define USM_KV  (TQ*SKS)                    // 21760
#define USM_W   (USM_KV + TK*SKS)           // 43520
#define USM_M   (USM_W + TQ*WS)             // 47872
#define USM_A   (USM_M + TQ)
#define USM_SUM (USM_A + TK)
#define USM_TOT (USM_SUM + TQ)
#define ATTN_SMEM_BYTES (USM_TOT * 4)       // 192,256 B

// ---------------- device scratch (no allocs allowed) ----------------
__device__ float g_xinner[TOT * H2n];  // up-proj output: [x_m | z]
__device__ float g_act   [TOT * Hn];   // silu(conv(x_m))
__device__ float g_q     [TOT * Hn];   // fp32 (for gates)
__device__ float g_k     [TOT * Hn];
__device__ float g_v     [TOT * Hn];
__device__ float g_qt    [TOT * Hn];   // tf32-exact copies (for attention)
__device__ float g_kt    [TOT * Hn];
__device__ float g_vt    [TOT * Hn];
__device__ float g_h     [TOT * Hn];   // mLSTM cell output
__device__ float g_hst   [TOT * Hn];   // post-LN/skip/gate, tf32-exact (down-GEMM A)
__device__ float g_xt    [TOT * En];   // tf32-exact x       (up-GEMM A)
__device__ float g_wut   [En * H2n];   // tf32-exact W_up    (up-GEMM B)
__device__ float g_wdt   [Hn * En];    // tf32-exact W_down  (down-GEMM B)
__device__ float g_ig    [Bn*NHn*Sn];
__device__ float g_lf    [Bn*NHn*Sn];  // logsigmoid(fg)
__device__ float g_a     [Bn*NHn*Sn];  // a_t = ig_t - c_t
__device__ float g_M     [Bn*NHn*Sn];  // running max of a
__device__ float g_nfl   [Bn*NHn*Sn];  // exp(-m_s)

// ---------------- tf32 helpers ----------------
__device__ __forceinline__ uint32_t f2tf32(float x) {
    uint32_t r;
    asm("cvt.rna.tf32.f32 %0, %1;" : "=r"(r) : "f"(x));
    return r;
}

__device__ __forceinline__ void mma_tf32(float* c, const uint32_t* a, const uint32_t* b) {
    asm volatile(
        "mma.sync.aligned.m16n8k8.row.col.f32.tf32.tf32.f32 "
        "{%0,%1,%2,%3}, {%4,%5,%6,%7}, {%8,%9}, {%0,%1,%2,%3};\n"
        : "+f"(c[0]), "+f"(c[1]), "+f"(c[2]), "+f"(c[3])
        : "r"(a[0]), "r"(a[1]), "r"(a[2]), "r"(a[3]), "r"(b[0]), "r"(b[1]));
}

// ---------------- elementwise tf32 rounding copy ----------------
__global__ void cvt_tf32_kernel(const float* __restrict__ src,
                                float* __restrict__ dst, int n4) {
    int i = blockIdx.x * blockDim.x + threadIdx.x;
    if (i >= n4) return;
    float4 v = ((const float4*)src)[i];
    uint4 t = make_uint4(f2tf32(v.x), f2tf32(v.y), f2tf32(v.z), f2tf32(v.w));
    ((uint4*)dst)[i] = t;
}

// ---------------- tensor-core tf32 GEMM: C = A(MxK) @ B(KxN), row-major ----------------
// A and B are PRE-CONVERTED tf32-exact fp32 arrays: staging is a pure copy.
#define ASTRIDE 20
#define BSTRIDE 136
__global__ __launch_bounds__(256) void mma_gemm_kernel(
    const float* __restrict__ A, const float* __restrict__ B,
    float* __restrict__ C, int M, int N, int K)
{
    __shared__ uint32_t As[2][128 * ASTRIDE];
    __shared__ uint32_t Bs[2][16 * BSTRIDE];

    int tid  = threadIdx.x;
    int lane = tid & 31, warp = tid >> 5;
    int wm = warp & 1, wn = warp >> 1;
    int bx = blockIdx.x, by = blockIdx.y;

    int ar  = tid & 127;
    int ach = tid >> 7;
    int br  = tid >> 4;
    int bc  = (tid & 15) * 8;

    const uint4* Ap = (const uint4*)(A + (size_t)(by * 128 + ar) * K + ach * 8);
    const uint4* Bp = (const uint4*)(B + (size_t)br * N + bx * 128 + bc);

    float acc[4][4][4];
    #pragma unroll
    for (int mt = 0; mt < 4; mt++)
        #pragma unroll
        for (int nt = 0; nt < 4; nt++)
            #pragma unroll
            for (int e = 0; e < 4; e++) acc[mt][nt][e] = 0.f;

    int nk = K >> 4;
    uint4 ra0, ra1, rb0, rb1;

    // prologue: load k-tile 0 (pure copy, no cvt)
    ra0 = Ap[0];
    ra1 = Ap[1];
    rb0 = Bp[0];
    rb1 = Bp[1];
    {
        int ab = ar * ASTRIDE + ach * 8;
        As[0][ab + 0] = ra0.x; As[0][ab + 1] = ra0.y;
        As[0][ab + 2] = ra0.z; As[0][ab + 3] = ra0.w;
        As[0][ab + 4] = ra1.x; As[0][ab + 5] = ra1.y;
        As[0][ab + 6] = ra1.z; As[0][ab + 7] = ra1.w;
        int bb = br * BSTRIDE + bc;
        *(uint4*)&Bs[0][bb]     = rb0;
        *(uint4*)&Bs[0][bb + 4] = rb1;
    }
    __syncthreads();

    int p = 0;
    for (int k0 = 0; k0 < nk; k0++) {
        if (k0 + 1 < nk) {
            const uint4* An  = (const uint4*)((const float*)Ap + (size_t)(k0 + 1) * 16);
            const uint4* Bnp = (const uint4*)((const float*)Bp + (size_t)(k0 + 1) * 16 * N);
            ra0 = An[0];
            ra1 = An[1];
            rb0 = Bnp[0];
            rb1 = Bnp[1];
        }
        #pragma unroll
        for (int h = 0; h < 2; h++) {
            int kb = h * 8 + (lane & 3);
            uint32_t af[4][4], bf[4][2];
            #pragma unroll
            for (int mt = 0; mt < 4; mt++) {
                int m = wm * 64 + mt * 16 + (lane >> 2);
                af[mt][0] = As[p][m * ASTRIDE + kb];
                af[mt][1] = As[p][(m + 8) * ASTRIDE + kb];
                af[mt][2] = As[p][m * ASTRIDE + kb + 4];
                af[mt][3] = As[p][(m + 8) * ASTRIDE + kb + 4];
            }
            #pragma unroll
            for (int nt = 0; nt < 4; nt++) {
                int n = wn * 32 + nt * 8 + (lane >> 2);
                bf[nt][0] = Bs[p][kb * BSTRIDE + n];
                bf[nt][1] = Bs[p][(kb + 4) * BSTRIDE + n];
            }
            #pragma unroll
            for (int mt = 0; mt < 4; mt++)
                #pragma unroll
                for (int nt = 0; nt < 4; nt++)
                    mma_tf32(acc[mt][nt], af[mt], bf[nt]);
        }
        if (k0 + 1 < nk) {
            int q = p ^ 1;
            int ab = ar * ASTRIDE + ach * 8;
            As[q][ab + 0] = ra0.x; As[q][ab + 1] = ra0.y;
            As[q][ab + 2] = ra0.z; As[q][ab + 3] = ra0.w;
            As[q][ab + 4] = ra1.x; As[q][ab + 5] = ra1.y;
            As[q][ab + 6] = ra1.z; As[q][ab + 7] = ra1.w;
            int bb = br * BSTRIDE + bc;
            *(uint4*)&Bs[q][bb]     = rb0;
            *(uint4*)&Bs[q][bb + 4] = rb1;
            __syncthreads();
            p = q;
        }
    }

    #pragma unroll
    for (int mt = 0; mt < 4; mt++) {
        int row = by * 128 + wm * 64 + mt * 16 + (lane >> 2);
        #pragma unroll
        for (int nt = 0; nt < 4; nt++) {
            int col = bx * 128 + wn * 32 + nt * 8 + 2 * (lane & 3);
            float2 v0 = make_float2(acc[mt][nt][0], acc[mt][nt][1]);
            float2 v1 = make_float2(acc[mt][nt][2], acc[mt][nt][3]);
            *(float2*)&C[(size_t)row * N + col] = v0;
            *(float2*)&C[(size_t)(row + 8) * N + col] = v1;
        }
    }
}

// ---------------- fused: causal conv(K=4) + bias + SiLU + headwise qkv ----------------
// Writes fp32 q,k,v (for gates) AND tf32-exact copies (for attention).
__global__ void conv_head_kernel(const float* __restrict__ conv_k,
                                 const float* __restrict__ conv_b,
                                 const float* __restrict__ Wq,
                                 const float* __restrict__ Wk,
                                 const float* __restrict__ Wv) {
    int idx = blockIdx.x * blockDim.x + threadIdx.x;
    if (idx >= TOT * NPH) return;
    int head = idx % NPH;
    int p = idx / NPH;
    int s = p % Sn;
    int h4 = head * 4;

    float4 bv = *(const float4*)&conv_b[h4];
    float a[4] = {bv.x, bv.y, bv.z, bv.w};
    float xv[4];
    #pragma unroll
    for (int j = 0; j < 4; j++) {
        int t = s - 3 + j;
        if (t >= 0) {
            float4 xm = *(const float4*)&g_xinner[(size_t)(p - s + t) * H2n + h4];
            float4 w  = *(const float4*)&conv_k[j * Hn + h4];
            a[0] += xm.x * w.x; a[1] += xm.y * w.y;
            a[2] += xm.z * w.z; a[3] += xm.w * w.w;
            if (j == 3) { xv[0] = xm.x; xv[1] = xm.y; xv[2] = xm.z; xv[3] = xm.w; }
        }
    }
    #pragma unroll
    for (int u = 0; u < 4; u++) a[u] = a[u] / (1.f + expf(-a[u]));
    *(float4*)&g_act[(size_t)p * Hn + h4] = make_float4(a[0], a[1], a[2], a[3]);

    float q[4] = {0, 0, 0, 0}, k[4] = {0, 0, 0, 0}, v[4] = {0, 0, 0, 0};
    #pragma unroll
    for (int d = 0; d < 4; d++) {
        float4 wq = *(const float4*)&Wq[head * 16 + d * 4];
        float4 wk = *(const float4*)&Wk[head * 16 + d * 4];
        float4 wv = *(const float4*)&Wv[head * 16 + d * 4];
        q[0] += a[d] * wq.x; q[1] += a[d] * wq.y; q[2] += a[d] * wq.z; q[3] += a[d] * wq.w;
        k[0] += a[d] * wk.x; k[1] += a[d] * wk.y; k[2] += a[d] * wk.z; k[3] += a[d] * wk.w;
        v[0] += xv[d] * wv.x; v[1] += xv[d] * wv.y; v[2] += xv[d] * wv.z; v[3] += xv[d] * wv.w;
    }
    size_t o = (size_t)p * Hn + h4;
    *(float4*)&g_q[o] = make_float4(q[0], q[1], q[2], q[3]);
    *(float4*)&g_k[o] = make_float4(k[0], k[1], k[2], k[3]);
    *(float4*)&g_v[o] = make_float4(v[0], v[1], v[2], v[3]);
    *(uint4*)&g_qt[o] = make_uint4(f2tf32(q[0]), f2tf32(q[1]), f2tf32(q[2]), f2tf32(q[3]));
    *(uint4*)&g_kt[o] = make_uint4(f2tf32(k[0]), f2tf32(k[1]), f2tf32(k[2]), f2tf32(k[3]));
    *(uint4*)&g_vt[o] = make_uint4(f2tf32(v[0]), f2tf32(v[1]), f2tf32(v[2]), f2tf32(v[3]));
}

// ---------------- input/forget gate projections ----------------
#define GR 4
__global__ void gates_kernel(const float* __restrict__ W_ig,
                             const float* __restrict__ b_ig,
                             const float* __restrict__ W_fg,
                             const float* __restrict__ b_fg) {
    int p0 = blockIdx.x * GR;
    int tid = threadIdx.x;       // 256
    int lane = tid & 31, warp = tid >> 5;
    float acc[GR][8];
    #pragma unroll
    for (int r = 0; r < GR; r++)
        #pragma unroll
        for (int v = 0; v < 8; v++) acc[r][v] = 0.f;

    const float4* wig4 = (const float4*)W_ig;
    const float4* wfg4 = (const float4*)W_fg;
    for (int i = tid; i < 3 * Hn; i += 256) {
        float4 wi = wig4[i];
        float4 wf = wfg4[i];
        const float* src;
        int off;
        if (i < Hn)          { src = g_q; off = i; }
        else if (i < 2 * Hn) { src = g_k; off = i - Hn; }
        else                 { src = g_v; off = i - 2 * Hn; }
        #pragma unroll
        for (int r = 0; r < GR; r++) {
            float g = src[(size_t)(p0 + r) * Hn + off];
            acc[r][0] += g * wi.x; acc[r][1] += g * wi.y;
            acc[r][2] += g * wi.z; acc[r][3] += g * wi.w;
            acc[r][4] += g * wf.x; acc[r][5] += g * wf.y;
            acc[r][6] += g * wf.z; acc[r][7] += g * wf.w;
        }
    }
    #pragma unroll
    for (int r = 0; r < GR; r++)
        #pragma unroll
        for (int v = 0; v < 8; v++)
            #pragma unroll
            for (int o = 16; o > 0; o >>= 1)
                acc[r][v] += __shfl_down_sync(0xffffffffu, acc[r][v], o);
    __shared__ float sred[8][32];
    if (lane == 0) {
        #pragma unroll
        for (int r = 0; r < GR; r++)
            #pragma unroll
            for (int v = 0; v < 8; v++)
                sred[warp][r * 8 + v] = acc[r][v];
    }
    __syncthreads();
    if (tid < 32) {
        float s = 0.f;
        #pragma unroll
        for (int w = 0; w < 8; w++) s += sred[w][tid];
        int r = tid >> 3, gsel = tid & 7;
        int pp = p0 + r;
        int b = pp / Sn, ss = pp % Sn;
        int n = gsel & 3;
        int o = (b * NHn + n) * Sn + ss;
        if (gsel < 4) {
            g_ig[o] = s + b_ig[n];
        } else {
            float fgv = s + b_fg[n];
            g_lf[o] = fminf(fgv, 0.f) - log1pf(expf(-fabsf(fgv)));
        }
    }
}

// ---------------- parallel scan per (b,n) ----------------
__global__ void scan_kernel() {
    __shared__ float sc[256];
    int bn = blockIdx.x;
    int tid = threadIdx.x;
    int off = bn * Sn + tid * 8;

    float locc[8];
    float run = 0.f;
    #pragma unroll
    for (int j = 0; j < 8; j++) { run += g_lf[off + j]; locc[j] = run; }

    sc[tid] = run;
    __syncthreads();
    for (int d = 1; d < 256; d <<= 1) {
        float add = (tid >= d) ? sc[tid - d] : 0.f;
        __syncthreads();
        sc[tid] += add;
        __syncthreads();
    }
    float coff = sc[tid] - run;

    float av[8];
    float rmax = -INFINITY;
    #pragma unroll
    for (int j = 0; j < 8; j++) {
        locc[j] += coff;
        av[j] = g_ig[off + j] - locc[j];
        rmax = fmaxf(rmax, av[j]);
    }
    __syncthreads();

    sc[tid] = rmax;
    __syncthreads();
    for (int d = 1; d < 256; d <<= 1) {
        float m = (tid >= d) ? sc[tid - d] : -INFINITY;
        __syncthreads();
        sc[tid] = fmaxf(sc[tid], m);
        __syncthreads();
    }
    float Mr = (tid == 0) ? -INFINITY : sc[tid - 1];

    #pragma unroll
    for (int j = 0; j < 8; j++) {
        Mr = fmaxf(Mr, av[j]);
        g_a[off + j] = av[j];
        g_M[off + j] = Mr;
        g_nfl[off + j] = expf(-(locc[j] + Mr));
    }
}

// ---------------- tensor-core tiled mLSTM cell (R11 structure, copy-only staging) ----------------
// grid: (NQT, B*NH), 256 threads = 8 warps (wm=warp>>1: 4 m16-rows; wn=warp&1: n halves).
__global__ __launch_bounds__(256) void attn_mma_kernel() {
    extern __shared__ uint32_t us[];
    uint32_t* sQ  = us + USM_Q;    // [64][SKS] tf32
    uint32_t* sKV = us + USM_KV;   // [64][SKS] tf32 (K then V per k-tile)
    uint32_t* sW  = us + USM_W;    // [64][WS]  tf32 weights
    float* sM   = (float*)(us + USM_M);
    float* sA   = (float*)(us + USM_A);
    float* sSum = (float*)(us + USM_SUM);

    int bn = blockIdx.y;
    int n = bn % NHn, b = bn / NHn;
    int qt = (NQT - 1) - blockIdx.x;   // longest blocks first
    int q0 = qt * TQ;
    int tid = threadIdx.x;
    int lane = tid & 31, warp = tid >> 5;
    int wm = warp >> 1, wn = warp & 1;
    int abase = bn * Sn;

    // stage Q (pre-converted: pure copy)
    for (int i = tid; i < TQ * DH4; i += 256) {
        int r = i / DH4, c = i % DH4;
        uint4 t = ((const uint4*)&g_qt[(size_t)(b * Sn + q0 + r) * Hn + n * DHn])[c];
        *(uint4*)&sQ[r * SKS + 4 * c] = t;
    }
    if (tid < TQ) {
        sM[tid] = g_M[abase + q0 + tid];
        sSum[tid] = 0.f;
    }
    __syncthreads();

    int r0 = wm * 16 + (lane >> 2);       // this thread's first C row
    float Ms0 = sM[r0], Ms1 = sM[r0 + 8];
    const float scale = rsqrtf((float)DHn);

    // PV accumulators: rows {r0, r0+8}, cols wn*168 + nt*8 + 2*(lane&3) (+1)
    float acc[21][4];
    #pragma unroll
    for (int nt = 0; nt < 21; nt++)
        #pragma unroll
        for (int e = 0; e < 4; e++) acc[nt][e] = 0.f;

    int nkt = qt + 1;
    for (int kt = 0; kt < nkt; kt++) {
        int k0 = kt * TK;
        __syncthreads();   // prior PV finished with sKV/sW
        // stage K (pure copy)
        for (int i = tid; i < TK * DH4; i += 256) {
            int r = i / DH4, c = i % DH4;
            uint4 t = ((const uint4*)&g_kt[(size_t)(b * Sn + k0 + r) * Hn + n * DHn])[c];
            *(uint4*)&sKV[r * SKS + 4 * c] = t;
        }
        if (tid < TK) sA[tid] = g_a[abase + k0 + tid];
        __syncthreads();

        // ---- QK^T: warp computes rows [wm*16, +16), keys [wn*32, +32) ----
        float wacc[4][4];
        #pragma unroll
        for (int nt = 0; nt < 4; nt++)
            #pragma unroll
            for (int e = 0; e < 4; e++) wacc[nt][e] = 0.f;

        #pragma unroll 2
        for (int c8 = 0; c8 < 42; c8++) {
            int cb = c8 * 8 + (lane & 3);
            uint32_t af[4];
            af[0] = sQ[r0 * SKS + cb];
            af[1] = sQ[(r0 + 8) * SKS + cb];
            af[2] = sQ[r0 * SKS + cb + 4];
            af[3] = sQ[(r0 + 8) * SKS + cb + 4];
            #pragma unroll
            for (int nt = 0; nt < 4; nt++) {
                int nn = wn * 32 + nt * 8 + (lane >> 2);
                uint32_t bf[2];
                bf[0] = sKV[nn * SKS + cb];
                bf[1] = sKV[nn * SKS + cb + 4];
                mma_tf32(wacc[nt], af, bf);
            }
        }

        // ---- postprocess: mask, scale*exp, tf32-round to sW, row sums ----
        float rs0 = 0.f, rs1 = 0.f;
        #pragma unroll
        for (int nt = 0; nt < 4; nt++) {
            int c0 = wn * 32 + nt * 8 + 2 * (lane & 3);
            int t0 = k0 + c0;
            float ea0 = sA[c0], ea1 = sA[c0 + 1];
            float w00 = (t0     <= q0 + r0)     ? wacc[nt][0] * scale * __expf(ea0 - Ms0) : 0.f;
            float w01 = (t0 + 1 <= q0 + r0)     ? wacc[nt][1] * scale * __expf(ea1 - Ms0) : 0.f;
            float w10 = (t0     <= q0 + r0 + 8) ? wacc[nt][2] * scale * __expf(ea0 - Ms1) : 0.f;
            float w11 = (t0 + 1 <= q0 + r0 + 8) ? wacc[nt][3] * scale * __expf(ea1 - Ms1) : 0.f;
            uint32_t u00 = f2tf32(w00), u01 = f2tf32(w01);
            uint32_t u10 = f2tf32(w10), u11 = f2tf32(w11);
            sW[r0 * WS + c0]           = u00;
            sW[r0 * WS + c0 + 1]       = u01;
            sW[(r0 + 8) * WS + c0]     = u10;
            sW[(r0 + 8) * WS + c0 + 1] = u11;
            rs0 += __uint_as_float(u00) + __uint_as_float(u01);
            rs1 += __uint_as_float(u10) + __uint_as_float(u11);
        }
        rs0 += __shfl_xor_sync(0xffffffffu, rs0, 1);
        rs0 += __shfl_xor_sync(0xffffffffu, rs0, 2);
        rs1 += __shfl_xor_sync(0xffffffffu, rs1, 1);
        rs1 += __shfl_xor_sync(0xffffffffu, rs1, 2);
        if ((lane & 3) == 0) {
            atomicAdd(&sSum[r0], rs0);
            atomicAdd(&sSum[r0 + 8], rs1);
        }
        __syncthreads();   // sW complete; sKV free

        // stage V (pure copy)
        for (int i = tid; i < TK * DH4; i += 256) {
            int r = i / DH4, c = i % DH4;
            uint4 t = ((const uint4*)&g_vt[(size_t)(b * Sn + k0 + r) * Hn + n * DHn])[c];
            *(uint4*)&sKV[r * SKS + 4 * c] = t;
        }
        __syncthreads();

        // ---- PV: warp computes rows [wm*16, +16), dims [wn*168, +168) ----
        #pragma unroll
        for (int k8 = 0; k8 < 8; k8++) {
            int tb = k8 * 8 + (lane & 3);
            uint32_t af[4];
            af[0] = sW[r0 * WS + tb];
            af[1] = sW[(r0 + 8) * WS + tb];
            af[2] = sW[r0 * WS + tb + 4];
            af[3] = sW[(r0 + 8) * WS + tb + 4];
            #pragma unroll
            for (int nt = 0; nt < 21; nt++) {
                int d = wn * 168 + nt * 8 + (lane >> 2);
                uint32_t bf[2];
                bf[0] = sKV[tb * SKS + d];
                bf[1] = sKV[(tb + 4) * SKS + d];
                mma_tf32(acc[nt], af, bf);
            }
        }
    }
    __syncthreads();

    // ---- epilogue: normalize and store (fp32, coalesced) ----
    float s0 = sSum[r0], s1 = sSum[r0 + 8];
    float inv0 = 1.f / (fmaxf(fabsf(s0), g_nfl[abase + q0 + r0]) + 1e-6f);
    float inv1 = 1.f / (fmaxf(fabsf(s1), g_nfl[abase + q0 + r0 + 8]) + 1e-6f);
    float* orow0 = &g_h[(size_t)(b * Sn + q0 + r0) * Hn + n * DHn];
    float* orow1 = &g_h[(size_t)(b * Sn + q0 + r0 + 8) * Hn + n * DHn];
    #pragma unroll
    for (int nt = 0; nt < 21; nt++) {
        int d = wn * 168 + nt * 8 + 2 * (lane & 3);
        *(float2*)&orow0[d] = make_float2(acc[nt][0] * inv0, acc[nt][1] * inv0);
        *(float2*)&orow1[d] = make_float2(acc[nt][2] * inv1, acc[nt][3] * inv1);
    }
}

// ---------------- per-head LN + skip + SiLU(z) gate (stores tf32-exact) ----------------
__global__ void ln_gate_kernel(const float* __restrict__ ln_w,
                               const float* __restrict__ skip) {
    int rid = blockIdx.x;
    int p = rid >> 2;
    int n = rid & 3;
    int tid = threadIdx.x;         // 128
    const float* hrow = &g_h[(size_t)p * Hn + n * DHn];

    float sum = 0.f, sq = 0.f;
    for (int d = tid; d < DHn; d += 128) {
        float v = hrow[d];
        sum += v; sq += v * v;
    }
    __shared__ float s1[4], s2[4], sbc[2];
    #pragma unroll
    for (int o = 16; o > 0; o >>= 1) {
        sum += __shfl_down_sync(0xffffffffu, sum, o);
        sq  += __shfl_down_sync(0xffffffffu, sq, o);
    }
    if ((tid & 31) == 0) { s1[tid >> 5] = sum; s2[tid >> 5] = sq; }
    __syncthreads();
    if (tid == 0) {
        float ts = s1[0] + s1[1] + s1[2] + s1[3];
        float tq = s2[0] + s2[1] + s2[2] + s2[3];
        float mu = ts / (float)DHn;
        float var = fmaxf(tq / (float)DHn - mu * mu, 0.f);
        sbc[0] = mu;
        sbc[1] = rsqrtf(var + 1e-5f);
    }
    __syncthreads();
    float mu = sbc[0], rs = sbc[1];
    for (int d = tid; d < DHn; d += 128) {
        int hidx = n * DHn + d;
        float hnv = (hrow[d] - mu) * rs * ln_w[hidx];
        float z = g_xinner[(size_t)p * H2n + Hn + hidx];
        float sz = z / (1.f + expf(-z));
        float o = (hnv + skip[hidx] * g_act[(size_t)p * Hn + hidx]) * sz;
        // store tf32-exact so down-GEMM staging is a pure copy (identical result:
        // down-GEMM previously applied this exact rounding during staging)
        ((uint32_t*)g_hst)[(size_t)p * Hn + hidx] = f2tf32(o);
    }
}

// ---------------- launch ----------------
extern "C" void kernel_launch(void* const* d_in, const int* in_sizes, int n_in,
                              void* d_out, int out_size) {
    const float* x      = (const float*)d_in[0];
    const float* W_up   = (const float*)d_in[1];
    const float* conv_k = (const float*)d_in[2];
    const float* conv_b = (const float*)d_in[3];
    const float* Wq     = (const float*)d_in[4];
    const float* Wk     = (const float*)d_in[5];
    const float* Wv     = (const float*)d_in[6];
    const float* W_ig   = (const float*)d_in[7];
    const float* b_ig   = (const float*)d_in[8];
    const float* W_fg   = (const float*)d_in[9];
    const float* b_fg   = (const float*)d_in[10];
    const float* ln_w   = (const float*)d_in[11];
    const float* skip   = (const float*)d_in[12];
    const float* W_down = (const float*)d_in[13];
    float* out = (float*)d_out;

    void *p_xinner = nullptr, *p_hst = nullptr, *p_xt = nullptr,
         *p_wut = nullptr, *p_wdt = nullptr;
    cudaGetSymbolAddress(&p_xinner, g_xinner);
    cudaGetSymbolAddress(&p_hst, g_hst);
    cudaGetSymbolAddress(&p_xt, g_xt);
    cudaGetSymbolAddress(&p_wut, g_wut);
    cudaGetSymbolAddress(&p_wdt, g_wdt);

    static bool attr_set = false;
    if (!attr_set) {
        cudaFuncSetAttribute(attn_mma_kernel,
                             cudaFuncAttributeMaxDynamicSharedMemorySize,
                             ATTN_SMEM_BYTES);
        attr_set = true;
    }

    // 0. one-time tf32 rounding of GEMM operands
    {
        int n4x = TOT * En / 4;
        cvt_tf32_kernel<<<(n4x + 255) / 256, 256>>>(x, (float*)p_xt, n4x);
        int n4u = En * H2n / 4;
        cvt_tf32_kernel<<<(n4u + 255) / 256, 256>>>(W_up, (float*)p_wut, n4u);
        int n4d = Hn * En / 4;
        cvt_tf32_kernel<<<(n4d + 255) / 256, 256>>>(W_down, (float*)p_wdt, n4d);
    }
    // 1. up projection: tf32 tensor cores, copy-only staging
    mma_gemm_kernel<<<dim3(H2n / 128, TOT / 128), 256>>>(
        (const float*)p_xt, (const float*)p_wut, (float*)p_xinner, TOT, H2n, En);
    // 2. fused conv + SiLU + headwise qkv (+ tf32 copies)
    {
        int nthr = TOT * NPH;
        conv_head_kernel<<<(nthr + 255) / 256, 256>>>(conv_k, conv_b, Wq, Wk, Wv);
    }
    // 3. gate projections
    gates_kernel<<<TOT / GR, 256>>>(W_ig, b_ig, W_fg, b_fg);
    // 4. per-(b,n) parallel scan
    scan_kernel<<<Bn * NHn, 256>>>();
    // 5. tensor-core tiled mLSTM cell
    attn_mma_kernel<<<dim3(NQT, Bn * NHn), 256, ATTN_SMEM_BYTES>>>();
    // 6. multi-head LN + skip + SiLU(z) gate (tf32-exact output)
    ln_gate_kernel<<<TOT * NHn, 128>>>(ln_w, skip);
    // 7. down projection: tf32 tensor cores, copy-only staging
    mma_gemm_kernel<<<dim3(En / 128, TOT / 128), 256>>>(
        (const float*)p_hst, (const float*)p_wdt, out, TOT, En, Hn);
}

// round 16
// speedup vs baseline: 1.1390x; 1.1390x over previous
#include <cuda_runtime.h>
#include <math.h>
#include <stdint.h>

// ---------------- problem constants ----------------
#define Bn   2
#define Sn   2048
#define En   1024
#define Hn   1344
#define H2n  2688
#define NHn  4
#define DHn  336
#define DH4  84           // DHn/4
#define NPH  (Hn/4)       // 336 projection heads
#define TOT  (Bn*Sn)      // 4096 rows

// attention tiling (tensor-core version)
#define TQ   64
#define TK   64
#define SKS  340          // u32 row stride for Q/K/V tf32 tiles (340%32=20 -> conflict-free)
#define WS   68           // u32 row stride for W tile (68%32=4 -> conflict-free)
#define NQT  (Sn/TQ)      // 32

// smem layout (u32 units)
#define USM_Q   0
#define USM_KV  (TQ*SKS)                    // 21760
#define USM_W   (USM_KV + TK*SKS)           // 43520
#define USM_M   (USM_W + TQ*WS)             // 47872
#define USM_A   (USM_M + TQ)
#define USM_SUM (USM_A + TK)
#define USM_TOT (USM_SUM + TQ)
#define ATTN_SMEM_BYTES (USM_TOT * 4)       // 192,256 B

// ---------------- device scratch (no allocs allowed) ----------------
__device__ float g_xinner[TOT * H2n];  // up-proj output: [x_m | z]
__device__ float g_act   [TOT * Hn];   // silu(conv(x_m))
__device__ float g_q     [TOT * Hn];
__device__ float g_k     [TOT * Hn];
__device__ float g_v     [TOT * Hn];
__device__ float g_h     [TOT * Hn];   // mLSTM cell output
__device__ float g_hst   [TOT * Hn];   // post-LN/skip/gate
__device__ float g_ig    [Bn*NHn*Sn];
__device__ float g_lf    [Bn*NHn*Sn];  // logsigmoid(fg)
__device__ float g_a     [Bn*NHn*Sn];  // a_t = ig_t - c_t
__device__ float g_M     [Bn*NHn*Sn];  // running max of a
__device__ float g_nfl   [Bn*NHn*Sn];  // exp(-m_s)

// ---------------- tf32 / ldmatrix helpers ----------------
__device__ __forceinline__ uint32_t f2tf32(float x) {
    uint32_t r;
    asm("cvt.rna.tf32.f32 %0, %1;" : "=r"(r) : "f"(x));
    return r;
}

__device__ __forceinline__ void mma_tf32(float* c, const uint32_t* a, const uint32_t* b) {
    asm volatile(
        "mma.sync.aligned.m16n8k8.row.col.f32.tf32.tf32.f32 "
        "{%0,%1,%2,%3}, {%4,%5,%6,%7}, {%8,%9}, {%0,%1,%2,%3};\n"
        : "+f"(c[0]), "+f"(c[1]), "+f"(c[2]), "+f"(c[3])
        : "r"(a[0]), "r"(a[1]), "r"(a[2]), "r"(a[3]), "r"(b[0]), "r"(b[1]));
}

__device__ __forceinline__ uint32_t smem_u32(const void* p) {
    return (uint32_t)__cvta_generic_to_shared(p);
}

// ldmatrix x4: four 8-row x 16-byte submatrices. For tf32 data, thread's reg q
// = tf32 element (row = lane>>2, col = lane&3) of submatrix q — exactly the
// m16n8k8 A-frag (and non-transposed B-frag) mapping.
__device__ __forceinline__ void ldsm_x4(uint32_t* r, uint32_t addr) {
    asm volatile("ldmatrix.sync.aligned.m8n8.x4.shared.b16 {%0,%1,%2,%3}, [%4];"
        : "=r"(r[0]), "=r"(r[1]), "=r"(r[2]), "=r"(r[3]) : "r"(addr));
}

// ---------------- tensor-core tf32 GEMM: C = A(MxK) @ B(KxN), row-major ----------------
#define ASTRIDE 20
#define BSTRIDE 136
__global__ __launch_bounds__(256) void mma_gemm_kernel(
    const float* __restrict__ A, const float* __restrict__ B,
    float* __restrict__ C, int M, int N, int K)
{
    __shared__ uint32_t As[2][128 * ASTRIDE];
    __shared__ uint32_t Bs[2][16 * BSTRIDE];

    int tid  = threadIdx.x;
    int lane = tid & 31, warp = tid >> 5;
    int wm = warp & 1, wn = warp >> 1;
    int bx = blockIdx.x, by = blockIdx.y;

    int ar  = tid & 127;
    int ach = tid >> 7;
    int br  = tid >> 4;
    int bc  = (tid & 15) * 8;

    const float* Ap = A + (size_t)(by * 128 + ar) * K + ach * 8;
    const float* Bp = B + (size_t)br * N + bx * 128 + bc;

    // ldmatrix A-frag addressing: thread supplies row (a_row + mt*16) at col (a_col + h*8)
    int jj = lane & 7, sel = lane >> 3;
    int a_row = wm * 64 + (sel & 1) * 8 + jj;
    int a_col = (sel >> 1) * 4;
    uint32_t abase0 = smem_u32(&As[0][a_row * ASTRIDE + a_col]);
    uint32_t abase1 = smem_u32(&As[1][a_row * ASTRIDE + a_col]);

    float acc[4][4][4];
    #pragma unroll
    for (int mt = 0; mt < 4; mt++)
        #pragma unroll
        for (int nt = 0; nt < 4; nt++)
            #pragma unroll
            for (int e = 0; e < 4; e++) acc[mt][nt][e] = 0.f;

    int nk = K >> 4;
    float4 ra0, ra1, rb0, rb1;

    // prologue: load + cvt + stage k-tile 0 (A via 2x STS.128, conflict-free)
    ra0 = *(const float4*)(Ap);
    ra1 = *(const float4*)(Ap + 4);
    rb0 = *(const float4*)(Bp);
    rb1 = *(const float4*)(Bp + 4);
    {
        uint4 ca0 = make_uint4(f2tf32(ra0.x), f2tf32(ra0.y), f2tf32(ra0.z), f2tf32(ra0.w));
        uint4 ca1 = make_uint4(f2tf32(ra1.x), f2tf32(ra1.y), f2tf32(ra1.z), f2tf32(ra1.w));
        uint4 cb0 = make_uint4(f2tf32(rb0.x), f2tf32(rb0.y), f2tf32(rb0.z), f2tf32(rb0.w));
        uint4 cb1 = make_uint4(f2tf32(rb1.x), f2tf32(rb1.y), f2tf32(rb1.z), f2tf32(rb1.w));
        int ab = ar * ASTRIDE + ach * 8;
        *(uint4*)&As[0][ab]     = ca0;
        *(uint4*)&As[0][ab + 4] = ca1;
        int bb = br * BSTRIDE + bc;
        *(uint4*)&Bs[0][bb]     = cb0;
        *(uint4*)&Bs[0][bb + 4] = cb1;
    }
    __syncthreads();

    int p = 0;
    for (int k0 = 0; k0 < nk; k0++) {
        if (k0 + 1 < nk) {
            const float* An = Ap + (size_t)(k0 + 1) * 16;
            const float* Bnp = Bp + (size_t)(k0 + 1) * 16 * N;
            ra0 = *(const float4*)(An);
            ra1 = *(const float4*)(An + 4);
            rb0 = *(const float4*)(Bnp);
            rb1 = *(const float4*)(Bnp + 4);
        }
        uint32_t abase = p ? abase1 : abase0;
        #pragma unroll
        for (int h = 0; h < 2; h++) {
            uint32_t af[4][4], bf[4][2];
            #pragma unroll
            for (int mt = 0; mt < 4; mt++)
                ldsm_x4(af[mt], abase + (uint32_t)(mt * 16 * ASTRIDE + h * 8) * 4u);
            int kb = h * 8 + (lane & 3);
            #pragma unroll
            for (int nt = 0; nt < 4; nt++) {
                int n = wn * 32 + nt * 8 + (lane >> 2);
                bf[nt][0] = Bs[p][kb * BSTRIDE + n];
                bf[nt][1] = Bs[p][(kb + 4) * BSTRIDE + n];
            }
            #pragma unroll
            for (int mt = 0; mt < 4; mt++)
                #pragma unroll
                for (int nt = 0; nt < 4; nt++)
                    mma_tf32(acc[mt][nt], af[mt], bf[nt]);
        }
        if (k0 + 1 < nk) {
            int q = p ^ 1;
            uint4 ca0 = make_uint4(f2tf32(ra0.x), f2tf32(ra0.y), f2tf32(ra0.z), f2tf32(ra0.w));
            uint4 ca1 = make_uint4(f2tf32(ra1.x), f2tf32(ra1.y), f2tf32(ra1.z), f2tf32(ra1.w));
            uint4 cb0 = make_uint4(f2tf32(rb0.x), f2tf32(rb0.y), f2tf32(rb0.z), f2tf32(rb0.w));
            uint4 cb1 = make_uint4(f2tf32(rb1.x), f2tf32(rb1.y), f2tf32(rb1.z), f2tf32(rb1.w));
            int ab = ar * ASTRIDE + ach * 8;
            *(uint4*)&As[q][ab]     = ca0;
            *(uint4*)&As[q][ab + 4] = ca1;
            int bb = br * BSTRIDE + bc;
            *(uint4*)&Bs[q][bb]     = cb0;
            *(uint4*)&Bs[q][bb + 4] = cb1;
            __syncthreads();
            p = q;
        }
    }

    #pragma unroll
    for (int mt = 0; mt < 4; mt++) {
        int row = by * 128 + wm * 64 + mt * 16 + (lane >> 2);
        #pragma unroll
        for (int nt = 0; nt < 4; nt++) {
            int col = bx * 128 + wn * 32 + nt * 8 + 2 * (lane & 3);
            float2 v0 = make_float2(acc[mt][nt][0], acc[mt][nt][1]);
            float2 v1 = make_float2(acc[mt][nt][2], acc[mt][nt][3]);
            *(float2*)&C[(size_t)row * N + col] = v0;
            *(float2*)&C[(size_t)(row + 8) * N + col] = v1;
        }
    }
}

// ---------------- fused: causal conv(K=4) + bias + SiLU + headwise qkv ----------------
__global__ void conv_head_kernel(const float* __restrict__ conv_k,
                                 const float* __restrict__ conv_b,
                                 const float* __restrict__ Wq,
                                 const float* __restrict__ Wk,
                                 const float* __restrict__ Wv) {
    int idx = blockIdx.x * blockDim.x + threadIdx.x;
    if (idx >= TOT * NPH) return;
    int head = idx % NPH;
    int p = idx / NPH;
    int s = p % Sn;
    int h4 = head * 4;

    float4 bv = *(const float4*)&conv_b[h4];
    float a[4] = {bv.x, bv.y, bv.z, bv.w};
    float xv[4];
    #pragma unroll
    for (int j = 0; j < 4; j++) {
        int t = s - 3 + j;
        if (t >= 0) {
            float4 xm = *(const float4*)&g_xinner[(size_t)(p - s + t) * H2n + h4];
            float4 w  = *(const float4*)&conv_k[j * Hn + h4];
            a[0] += xm.x * w.x; a[1] += xm.y * w.y;
            a[2] += xm.z * w.z; a[3] += xm.w * w.w;
            if (j == 3) { xv[0] = xm.x; xv[1] = xm.y; xv[2] = xm.z; xv[3] = xm.w; }
        }
    }
    #pragma unroll
    for (int u = 0; u < 4; u++) a[u] = a[u] / (1.f + expf(-a[u]));
    *(float4*)&g_act[(size_t)p * Hn + h4] = make_float4(a[0], a[1], a[2], a[3]);

    float q[4] = {0, 0, 0, 0}, k[4] = {0, 0, 0, 0}, v[4] = {0, 0, 0, 0};
    #pragma unroll
    for (int d = 0; d < 4; d++) {
        float4 wq = *(const float4*)&Wq[head * 16 + d * 4];
        float4 wk = *(const float4*)&Wk[head * 16 + d * 4];
        float4 wv = *(const float4*)&Wv[head * 16 + d * 4];
        q[0] += a[d] * wq.x; q[1] += a[d] * wq.y; q[2] += a[d] * wq.z; q[3] += a[d] * wq.w;
        k[0] += a[d] * wk.x; k[1] += a[d] * wk.y; k[2] += a[d] * wk.z; k[3] += a[d] * wk.w;
        v[0] += xv[d] * wv.x; v[1] += xv[d] * wv.y; v[2] += xv[d] * wv.z; v[3] += xv[d] * wv.w;
    }
    size_t o = (size_t)p * Hn + h4;
    *(float4*)&g_q[o] = make_float4(q[0], q[1], q[2], q[3]);
    *(float4*)&g_k[o] = make_float4(k[0], k[1], k[2], k[3]);
    *(float4*)&g_v[o] = make_float4(v[0], v[1], v[2], v[3]);
}

// ---------------- input/forget gate projections ----------------
#define GR 4
__global__ void gates_kernel(const float* __restrict__ W_ig,
                             const float* __restrict__ b_ig,
                             const float* __restrict__ W_fg,
                             const float* __restrict__ b_fg) {
    int p0 = blockIdx.x * GR;
    int tid = threadIdx.x;       // 256
    int lane = tid & 31, warp = tid >> 5;
    float acc[GR][8];
    #pragma unroll
    for (int r = 0; r < GR; r++)
        #pragma unroll
        for (int v = 0; v < 8; v++) acc[r][v] = 0.f;

    const float4* wig4 = (const float4*)W_ig;
    const float4* wfg4 = (const float4*)W_fg;
    for (int i = tid; i < 3 * Hn; i += 256) {
        float4 wi = wig4[i];
        float4 wf = wfg4[i];
        const float* src;
        int off;
        if (i < Hn)          { src = g_q; off = i; }
        else if (i < 2 * Hn) { src = g_k; off = i - Hn; }
        else                 { src = g_v; off = i - 2 * Hn; }
        #pragma unroll
        for (int r = 0; r < GR; r++) {
            float g = src[(size_t)(p0 + r) * Hn + off];
            acc[r][0] += g * wi.x; acc[r][1] += g * wi.y;
            acc[r][2] += g * wi.z; acc[r][3] += g * wi.w;
            acc[r][4] += g * wf.x; acc[r][5] += g * wf.y;
            acc[r][6] += g * wf.z; acc[r][7] += g * wf.w;
        }
    }
    #pragma unroll
    for (int r = 0; r < GR; r++)
        #pragma unroll
        for (int v = 0; v < 8; v++)
            #pragma unroll
            for (int o = 16; o > 0; o >>= 1)
                acc[r][v] += __shfl_down_sync(0xffffffffu, acc[r][v], o);
    __shared__ float sred[8][32];
    if (lane == 0) {
        #pragma unroll
        for (int r = 0; r < GR; r++)
            #pragma unroll
            for (int v = 0; v < 8; v++)
                sred[warp][r * 8 + v] = acc[r][v];
    }
    __syncthreads();
    if (tid < 32) {
        float s = 0.f;
        #pragma unroll
        for (int w = 0; w < 8; w++) s += sred[w][tid];
        int r = tid >> 3, gsel = tid & 7;
        int pp = p0 + r;
        int b = pp / Sn, ss = pp % Sn;
        int n = gsel & 3;
        int o = (b * NHn + n) * Sn + ss;
        if (gsel < 4) {
            g_ig[o] = s + b_ig[n];
        } else {
            float fgv = s + b_fg[n];
            g_lf[o] = fminf(fgv, 0.f) - log1pf(expf(-fabsf(fgv)));
        }
    }
}

// ---------------- parallel scan per (b,n) ----------------
__global__ void scan_kernel() {
    __shared__ float sc[256];
    int bn = blockIdx.x;
    int tid = threadIdx.x;
    int off = bn * Sn + tid * 8;

    float locc[8];
    float run = 0.f;
    #pragma unroll
    for (int j = 0; j < 8; j++) { run += g_lf[off + j]; locc[j] = run; }

    sc[tid] = run;
    __syncthreads();
    for (int d = 1; d < 256; d <<= 1) {
        float add = (tid >= d) ? sc[tid - d] : 0.f;
        __syncthreads();
        sc[tid] += add;
        __syncthreads();
    }
    float coff = sc[tid] - run;

    float av[8];
    float rmax = -INFINITY;
    #pragma unroll
    for (int j = 0; j < 8; j++) {
        locc[j] += coff;
        av[j] = g_ig[off + j] - locc[j];
        rmax = fmaxf(rmax, av[j]);
    }
    __syncthreads();

    sc[tid] = rmax;
    __syncthreads();
    for (int d = 1; d < 256; d <<= 1) {
        float m = (tid >= d) ? sc[tid - d] : -INFINITY;
        __syncthreads();
        sc[tid] = fmaxf(sc[tid], m);
        __syncthreads();
    }
    float Mr = (tid == 0) ? -INFINITY : sc[tid - 1];

    #pragma unroll
    for (int j = 0; j < 8; j++) {
        Mr = fmaxf(Mr, av[j]);
        g_a[off + j] = av[j];
        g_M[off + j] = Mr;
        g_nfl[off + j] = expf(-(locc[j] + Mr));
    }
}

// ---------------- tensor-core tiled mLSTM cell (ldmatrix fragment loads) ----------------
// grid: (NQT, B*NH), 256 threads = 8 warps (wm=warp>>1: 4 m16-rows; wn=warp&1: n halves).
__global__ __launch_bounds__(256) void attn_mma_kernel() {
    extern __shared__ uint32_t us[];
    uint32_t* sQ  = us + USM_Q;    // [64][SKS] tf32
    uint32_t* sKV = us + USM_KV;   // [64][SKS] tf32 (K then V per k-tile)
    uint32_t* sW  = us + USM_W;    // [64][WS]  tf32 weights
    float* sM   = (float*)(us + USM_M);
    float* sA   = (float*)(us + USM_A);
    float* sSum = (float*)(us + USM_SUM);

    int bn = blockIdx.y;
    int n = bn % NHn, b = bn / NHn;
    int qt = (NQT - 1) - blockIdx.x;   // longest blocks first
    int q0 = qt * TQ;
    int tid = threadIdx.x;
    int lane = tid & 31, warp = tid >> 5;
    int wm = warp >> 1, wn = warp & 1;
    int abase = bn * Sn;

    // stage Q (cvt to tf32)
    for (int i = tid; i < TQ * DH4; i += 256) {
        int r = i / DH4, c = i % DH4;
        float4 v = ((const float4*)&g_q[(size_t)(b * Sn + q0 + r) * Hn + n * DHn])[c];
        uint4 t = make_uint4(f2tf32(v.x), f2tf32(v.y), f2tf32(v.z), f2tf32(v.w));
        *(uint4*)&sQ[r * SKS + 4 * c] = t;
    }
    if (tid < TQ) {
        sM[tid] = g_M[abase + q0 + tid];
        sSum[tid] = 0.f;
    }
    __syncthreads();

    int r0 = wm * 16 + (lane >> 2);       // this thread's first C row
    float Ms0 = sM[r0], Ms1 = sM[r0 + 8];
    const float scale = rsqrtf((float)DHn);

    // ldmatrix addressing
    int jj = lane & 7, sel = lane >> 3;
    uint32_t qbase = smem_u32(&sQ[(wm * 16 + (sel & 1) * 8 + jj) * SKS + (sel >> 1) * 4]);
    uint32_t kbase = smem_u32(&sKV[(wn * 32 + sel * 8 + jj) * SKS]);
    uint32_t wbase = smem_u32(&sW[(wm * 16 + (sel & 1) * 8 + jj) * WS + (sel >> 1) * 4]);

    // PV accumulators: rows {r0, r0+8}, cols wn*168 + nt*8 + 2*(lane&3) (+1)
    float acc[21][4];
    #pragma unroll
    for (int nt = 0; nt < 21; nt++)
        #pragma unroll
        for (int e = 0; e < 4; e++) acc[nt][e] = 0.f;

    int nkt = qt + 1;
    for (int kt = 0; kt < nkt; kt++) {
        int k0 = kt * TK;
        __syncthreads();   // prior PV finished with sKV/sW
        // stage K (cvt to tf32)
        for (int i = tid; i < TK * DH4; i += 256) {
            int r = i / DH4, c = i % DH4;
            float4 v = ((const float4*)&g_k[(size_t)(b * Sn + k0 + r) * Hn + n * DHn])[c];
            uint4 t = make_uint4(f2tf32(v.x), f2tf32(v.y), f2tf32(v.z), f2tf32(v.w));
            *(uint4*)&sKV[r * SKS + 4 * c] = t;
        }
        if (tid < TK) sA[tid] = g_a[abase + k0 + tid];
        __syncthreads();

        // ---- QK^T: warp computes rows [wm*16, +16), keys [wn*32, +32) ----
        float wacc[4][4];
        #pragma unroll
        for (int nt = 0; nt < 4; nt++)
            #pragma unroll
            for (int e = 0; e < 4; e++) wacc[nt][e] = 0.f;

        #pragma unroll 2
        for (int c8 = 0; c8 < 42; c8++) {
            uint32_t af[4], bf0[4], bf1[4];
            ldsm_x4(af,  qbase + (uint32_t)c8 * 32u);
            ldsm_x4(bf0, kbase + (uint32_t)c8 * 32u);
            ldsm_x4(bf1, kbase + (uint32_t)c8 * 32u + 16u);
            #pragma unroll
            for (int nt = 0; nt < 4; nt++) {
                uint32_t b2[2] = {bf0[nt], bf1[nt]};
                mma_tf32(wacc[nt], af, b2);
            }
        }

        // ---- postprocess: mask, scale*exp, tf32-round to sW, row sums ----
        float rs0 = 0.f, rs1 = 0.f;
        #pragma unroll
        for (int nt = 0; nt < 4; nt++) {
            int c0 = wn * 32 + nt * 8 + 2 * (lane & 3);
            int t0 = k0 + c0;
            float ea0 = sA[c0], ea1 = sA[c0 + 1];
            float w00 = (t0     <= q0 + r0)     ? wacc[nt][0] * scale * __expf(ea0 - Ms0) : 0.f;
            float w01 = (t0 + 1 <= q0 + r0)     ? wacc[nt][1] * scale * __expf(ea1 - Ms0) : 0.f;
            float w10 = (t0     <= q0 + r0 + 8) ? wacc[nt][2] * scale * __expf(ea0 - Ms1) : 0.f;
            float w11 = (t0 + 1 <= q0 + r0 + 8) ? wacc[nt][3] * scale * __expf(ea1 - Ms1) : 0.f;
            uint32_t u00 = f2tf32(w00), u01 = f2tf32(w01);
            uint32_t u10 = f2tf32(w10), u11 = f2tf32(w11);
            sW[r0 * WS + c0]           = u00;
            sW[r0 * WS + c0 + 1]       = u01;
            sW[(r0 + 8) * WS + c0]     = u10;
            sW[(r0 + 8) * WS + c0 + 1] = u11;
            rs0 += __uint_as_float(u00) + __uint_as_float(u01);
            rs1 += __uint_as_float(u10) + __uint_as_float(u11);
        }
        rs0 += __shfl_xor_sync(0xffffffffu, rs0, 1);
        rs0 += __shfl_xor_sync(0xffffffffu, rs0, 2);
        rs1 += __shfl_xor_sync(0xffffffffu, rs1, 1);
        rs1 += __shfl_xor_sync(0xffffffffu, rs1, 2);
        if ((lane & 3) == 0) {
            atomicAdd(&sSum[r0], rs0);
            atomicAdd(&sSum[r0 + 8], rs1);
        }
        __syncthreads();   // sW complete; sKV free

        // stage V (cvt to tf32)
        for (int i = tid; i < TK * DH4; i += 256) {
            int r = i / DH4, c = i % DH4;
            float4 v = ((const float4*)&g_v[(size_t)(b * Sn + k0 + r) * Hn + n * DHn])[c];
            uint4 t = make_uint4(f2tf32(v.x), f2tf32(v.y), f2tf32(v.z), f2tf32(v.w));
            *(uint4*)&sKV[r * SKS + 4 * c] = t;
        }
        __syncthreads();

        // ---- PV: warp computes rows [wm*16, +16), dims [wn*168, +168) ----
        #pragma unroll
        for (int k8 = 0; k8 < 8; k8++) {
            uint32_t af[4];
            ldsm_x4(af, wbase + (uint32_t)k8 * 32u);
            int tb = k8 * 8 + (lane & 3);
            #pragma unroll
            for (int nt = 0; nt < 21; nt++) {
                int d = wn * 168 + nt * 8 + (lane >> 2);
                uint32_t bf[2];
                bf[0] = sKV[tb * SKS + d];
                bf[1] = sKV[(tb + 4) * SKS + d];
                mma_tf32(acc[nt], af, bf);
            }
        }
    }
    __syncthreads();

    // ---- epilogue: normalize and store ----
    float s0 = sSum[r0], s1 = sSum[r0 + 8];
    float inv0 = 1.f / (fmaxf(fabsf(s0), g_nfl[abase + q0 + r0]) + 1e-6f);
    float inv1 = 1.f / (fmaxf(fabsf(s1), g_nfl[abase + q0 + r0 + 8]) + 1e-6f);
    float* orow0 = &g_h[(size_t)(b * Sn + q0 + r0) * Hn + n * DHn];
    float* orow1 = &g_h[(size_t)(b * Sn + q0 + r0 + 8) * Hn + n * DHn];
    #pragma unroll
    for (int nt = 0; nt < 21; nt++) {
        int d = wn * 168 + nt * 8 + 2 * (lane & 3);
        *(float2*)&orow0[d] = make_float2(acc[nt][0] * inv0, acc[nt][1] * inv0);
        *(float2*)&orow1[d] = make_float2(acc[nt][2] * inv1, acc[nt][3] * inv1);
    }
}

// ---------------- per-head LN + skip + SiLU(z) gate ----------------
__global__ void ln_gate_kernel(const float* __restrict__ ln_w,
                               const float* __restrict__ skip) {
    int rid = blockIdx.x;
    int p = rid >> 2;
    int n = rid & 3;
    int tid = threadIdx.x;         // 128
    const float* hrow = &g_h[(size_t)p * Hn + n * DHn];

    float sum = 0.f, sq = 0.f;
    for (int d = tid; d < DHn; d += 128) {
        float v = hrow[d];
        sum += v; sq += v * v;
    }
    __shared__ float s1[4], s2[4], sbc[2];
    #pragma unroll
    for (int o = 16; o > 0; o >>= 1) {
        sum += __shfl_down_sync(0xffffffffu, sum, o);
        sq  += __shfl_down_sync(0xffffffffu, sq, o);
    }
    if ((tid & 31) == 0) { s1[tid >> 5] = sum; s2[tid >> 5] = sq; }
    __syncthreads();
    if (tid == 0) {
        float ts = s1[0] + s1[1] + s1[2] + s1[3];
        float tq = s2[0] + s2[1] + s2[2] + s2[3];
        float mu = ts / (float)DHn;
        float var = fmaxf(tq / (float)DHn - mu * mu, 0.f);
        sbc[0] = mu;
        sbc[1] = rsqrtf(var + 1e-5f);
    }
    __syncthreads();
    float mu = sbc[0], rs = sbc[1];
    for (int d = tid; d < DHn; d += 128) {
        int hidx = n * DHn + d;
        float hnv = (hrow[d] - mu) * rs * ln_w[hidx];
        float z = g_xinner[(size_t)p * H2n + Hn + hidx];
        float sz = z / (1.f + expf(-z));
        g_hst[(size_t)p * Hn + hidx] = (hnv + skip[hidx] * g_act[(size_t)p * Hn + hidx]) * sz;
    }
}

// ---------------- launch ----------------
extern "C" void kernel_launch(void* const* d_in, const int* in_sizes, int n_in,
                              void* d_out, int out_size) {
    const float* x      = (const float*)d_in[0];
    const float* W_up   = (const float*)d_in[1];
    const float* conv_k = (const float*)d_in[2];
    const float* conv_b = (const float*)d_in[3];
    const float* Wq     = (const float*)d_in[4];
    const float* Wk     = (const float*)d_in[5];
    const float* Wv     = (const float*)d_in[6];
    const float* W_ig   = (const float*)d_in[7];
    const float* b_ig   = (const float*)d_in[8];
    const float* W_fg   = (const float*)d_in[9];
    const float* b_fg   = (const float*)d_in[10];
    const float* ln_w   = (const float*)d_in[11];
    const float* skip   = (const float*)d_in[12];
    const float* W_down = (const float*)d_in[13];
    float* out = (float*)d_out;

    void *p_xinner = nullptr, *p_hst = nullptr;
    cudaGetSymbolAddress(&p_xinner, g_xinner);
    cudaGetSymbolAddress(&p_hst, g_hst);

    static bool attr_set = false;
    if (!attr_set) {
        cudaFuncSetAttribute(attn_mma_kernel,
                             cudaFuncAttributeMaxDynamicSharedMemorySize,
                             ATTN_SMEM_BYTES);
        attr_set = true;
    }

    // 1. up projection: (4096x1024) @ (1024x2688) — tf32 tensor cores
    mma_gemm_kernel<<<dim3(H2n / 128, TOT / 128), 256>>>(x, W_up, (float*)p_xinner,
                                                         TOT, H2n, En);
    // 2. fused conv + SiLU + headwise qkv
    {
        int nthr = TOT * NPH;
        conv_head_kernel<<<(nthr + 255) / 256, 256>>>(conv_k, conv_b, Wq, Wk, Wv);
    }
    // 3. gate projections
    gates_kernel<<<TOT / GR, 256>>>(W_ig, b_ig, W_fg, b_fg);
    // 4. per-(b,n) parallel scan
    scan_kernel<<<Bn * NHn, 256>>>();
    // 5. tensor-core tiled mLSTM cell (ldmatrix)
    attn_mma_kernel<<<dim3(NQT, Bn * NHn), 256, ATTN_SMEM_BYTES>>>();
    // 6. multi-head LN + skip + SiLU(z) gate
    ln_gate_kernel<<<TOT * NHn, 128>>>(ln_w, skip);
    // 7. down projection: (4096x1344) @ (1344x1024) — tf32 tensor cores
    mma_gemm_kernel<<<dim3(En / 128, TOT / 128), 256>>>((const float*)p_hst, W_down,
                                                        out, TOT, En, Hn);
}

// round 17
// speedup vs baseline: 1.2628x; 1.1087x over previous
#include <cuda_runtime.h>
#include <math.h>
#include <stdint.h>

// ---------------- problem constants ----------------
#define Bn   2
#define Sn   2048
#define En   1024
#define Hn   1344
#define H2n  2688
#define NHn  4
#define DHn  336
#define DH4  84           // DHn/4
#define NPH  (Hn/4)       // 336 projection heads
#define TOT  (Bn*Sn)      // 4096 rows

// attention tiling (tensor-core version)
#define TQ   64
#define TK   64
#define SKS  340          // u32 row stride for Q/K/V tf32 tiles (340%32=20 -> conflict-free)
#define WS   68           // u32 row stride for W tile (68%32=4 -> conflict-free)
#define NQT  (Sn/TQ)      // 32

// smem layout (u32 units)
#define USM_Q   0
#define USM_KV  (TQ*SKS)                    // 21760
#define USM_W   (USM_KV + TK*SKS)           // 43520
#define USM_M   (USM_W + TQ*WS)             // 47872
#define USM_A   (USM_M + TQ)
#define USM_SUM (USM_A + TK)
#define USM_TOT (USM_SUM + TQ)
#define ATTN_SMEM_BYTES (USM_TOT * 4)       // 192,256 B

// ---------------- device scratch (no allocs allowed) ----------------
__device__ float g_xinner[TOT * H2n];  // up-proj output: [x_m | z]
__device__ float g_act   [TOT * Hn];   // silu(conv(x_m))
__device__ float g_q     [TOT * Hn];   // fp32 (gates)
__device__ float g_k     [TOT * Hn];
__device__ float g_v     [TOT * Hn];
__device__ float g_qt    [TOT * Hn];   // tf32-exact shadows (attention; cp.async staging)
__device__ float g_kt    [TOT * Hn];
__device__ float g_vt    [TOT * Hn];
__device__ float g_h     [TOT * Hn];   // mLSTM cell output
__device__ float g_hst   [TOT * Hn];   // post-LN/skip/gate
__device__ float g_ig    [Bn*NHn*Sn];
__device__ float g_lf    [Bn*NHn*Sn];  // logsigmoid(fg)
__device__ float g_a     [Bn*NHn*Sn];  // a_t = ig_t - c_t
__device__ float g_M     [Bn*NHn*Sn];  // running max of a
__device__ float g_nfl   [Bn*NHn*Sn];  // exp(-m_s)

// ---------------- tf32 / ldmatrix / cp.async helpers ----------------
__device__ __forceinline__ uint32_t f2tf32(float x) {
    uint32_t r;
    asm("cvt.rna.tf32.f32 %0, %1;" : "=r"(r) : "f"(x));
    return r;
}

__device__ __forceinline__ void mma_tf32(float* c, const uint32_t* a, const uint32_t* b) {
    asm volatile(
        "mma.sync.aligned.m16n8k8.row.col.f32.tf32.tf32.f32 "
        "{%0,%1,%2,%3}, {%4,%5,%6,%7}, {%8,%9}, {%0,%1,%2,%3};\n"
        : "+f"(c[0]), "+f"(c[1]), "+f"(c[2]), "+f"(c[3])
        : "r"(a[0]), "r"(a[1]), "r"(a[2]), "r"(a[3]), "r"(b[0]), "r"(b[1]));
}

__device__ __forceinline__ uint32_t smem_u32(const void* p) {
    return (uint32_t)__cvta_generic_to_shared(p);
}

__device__ __forceinline__ void ldsm_x4(uint32_t* r, uint32_t addr) {
    asm volatile("ldmatrix.sync.aligned.m8n8.x4.shared.b16 {%0,%1,%2,%3}, [%4];"
        : "=r"(r[0]), "=r"(r[1]), "=r"(r[2]), "=r"(r[3]) : "r"(addr));
}

__device__ __forceinline__ void cp16(uint32_t smem_dst, const void* gsrc) {
    asm volatile("cp.async.cg.shared.global [%0], [%1], 16;"
                 :: "r"(smem_dst), "l"(gsrc));
}
__device__ __forceinline__ void cp_commit() {
    asm volatile("cp.async.commit_group;" ::: "memory");
}
__device__ __forceinline__ void cp_wait0() {
    asm volatile("cp.async.wait_group 0;" ::: "memory");
}

// ---------------- tensor-core tf32 GEMM: C = A(MxK) @ B(KxN), row-major ----------------
#define ASTRIDE 20
#define BSTRIDE 136
__global__ __launch_bounds__(256) void mma_gemm_kernel(
    const float* __restrict__ A, const float* __restrict__ B,
    float* __restrict__ C, int M, int N, int K)
{
    __shared__ uint32_t As[2][128 * ASTRIDE];
    __shared__ uint32_t Bs[2][16 * BSTRIDE];

    int tid  = threadIdx.x;
    int lane = tid & 31, warp = tid >> 5;
    int wm = warp & 1, wn = warp >> 1;
    int bx = blockIdx.x, by = blockIdx.y;

    int ar  = tid & 127;
    int ach = tid >> 7;
    int br  = tid >> 4;
    int bc  = (tid & 15) * 8;

    const float* Ap = A + (size_t)(by * 128 + ar) * K + ach * 8;
    const float* Bp = B + (size_t)br * N + bx * 128 + bc;

    int jj = lane & 7, sel = lane >> 3;
    int a_row = wm * 64 + (sel & 1) * 8 + jj;
    int a_col = (sel >> 1) * 4;
    uint32_t abase0 = smem_u32(&As[0][a_row * ASTRIDE + a_col]);
    uint32_t abase1 = smem_u32(&As[1][a_row * ASTRIDE + a_col]);

    float acc[4][4][4];
    #pragma unroll
    for (int mt = 0; mt < 4; mt++)
        #pragma unroll
        for (int nt = 0; nt < 4; nt++)
            #pragma unroll
            for (int e = 0; e < 4; e++) acc[mt][nt][e] = 0.f;

    int nk = K >> 4;
    float4 ra0, ra1, rb0, rb1;

    ra0 = *(const float4*)(Ap);
    ra1 = *(const float4*)(Ap + 4);
    rb0 = *(const float4*)(Bp);
    rb1 = *(const float4*)(Bp + 4);
    {
        uint4 ca0 = make_uint4(f2tf32(ra0.x), f2tf32(ra0.y), f2tf32(ra0.z), f2tf32(ra0.w));
        uint4 ca1 = make_uint4(f2tf32(ra1.x), f2tf32(ra1.y), f2tf32(ra1.z), f2tf32(ra1.w));
        uint4 cb0 = make_uint4(f2tf32(rb0.x), f2tf32(rb0.y), f2tf32(rb0.z), f2tf32(rb0.w));
        uint4 cb1 = make_uint4(f2tf32(rb1.x), f2tf32(rb1.y), f2tf32(rb1.z), f2tf32(rb1.w));
        int ab = ar * ASTRIDE + ach * 8;
        *(uint4*)&As[0][ab]     = ca0;
        *(uint4*)&As[0][ab + 4] = ca1;
        int bb = br * BSTRIDE + bc;
        *(uint4*)&Bs[0][bb]     = cb0;
        *(uint4*)&Bs[0][bb + 4] = cb1;
    }
    __syncthreads();

    int p = 0;
    for (int k0 = 0; k0 < nk; k0++) {
        if (k0 + 1 < nk) {
            const float* An = Ap + (size_t)(k0 + 1) * 16;
            const float* Bnp = Bp + (size_t)(k0 + 1) * 16 * N;
            ra0 = *(const float4*)(An);
            ra1 = *(const float4*)(An + 4);
            rb0 = *(const float4*)(Bnp);
            rb1 = *(const float4*)(Bnp + 4);
        }
        uint32_t abase = p ? abase1 : abase0;
        #pragma unroll
        for (int h = 0; h < 2; h++) {
            uint32_t af[4][4], bf[4][2];
            #pragma unroll
            for (int mt = 0; mt < 4; mt++)
                ldsm_x4(af[mt], abase + (uint32_t)(mt * 16 * ASTRIDE + h * 8) * 4u);
            int kb = h * 8 + (lane & 3);
            #pragma unroll
            for (int nt = 0; nt < 4; nt++) {
                int n = wn * 32 + nt * 8 + (lane >> 2);
                bf[nt][0] = Bs[p][kb * BSTRIDE + n];
                bf[nt][1] = Bs[p][(kb + 4) * BSTRIDE + n];
            }
            #pragma unroll
            for (int mt = 0; mt < 4; mt++)
                #pragma unroll
                for (int nt = 0; nt < 4; nt++)
                    mma_tf32(acc[mt][nt], af[mt], bf[nt]);
        }
        if (k0 + 1 < nk) {
            int q = p ^ 1;
            uint4 ca0 = make_uint4(f2tf32(ra0.x), f2tf32(ra0.y), f2tf32(ra0.z), f2tf32(ra0.w));
            uint4 ca1 = make_uint4(f2tf32(ra1.x), f2tf32(ra1.y), f2tf32(ra1.z), f2tf32(ra1.w));
            uint4 cb0 = make_uint4(f2tf32(rb0.x), f2tf32(rb0.y), f2tf32(rb0.z), f2tf32(rb0.w));
            uint4 cb1 = make_uint4(f2tf32(rb1.x), f2tf32(rb1.y), f2tf32(rb1.z), f2tf32(rb1.w));
            int ab = ar * ASTRIDE + ach * 8;
            *(uint4*)&As[q][ab]     = ca0;
            *(uint4*)&As[q][ab + 4] = ca1;
            int bb = br * BSTRIDE + bc;
            *(uint4*)&Bs[q][bb]     = cb0;
            *(uint4*)&Bs[q][bb + 4] = cb1;
            __syncthreads();
            p = q;
        }
    }

    #pragma unroll
    for (int mt = 0; mt < 4; mt++) {
        int row = by * 128 + wm * 64 + mt * 16 + (lane >> 2);
        #pragma unroll
        for (int nt = 0; nt < 4; nt++) {
            int col = bx * 128 + wn * 32 + nt * 8 + 2 * (lane & 3);
            float2 v0 = make_float2(acc[mt][nt][0], acc[mt][nt][1]);
            float2 v1 = make_float2(acc[mt][nt][2], acc[mt][nt][3]);
            *(float2*)&C[(size_t)row * N + col] = v0;
            *(float2*)&C[(size_t)(row + 8) * N + col] = v1;
        }
    }
}

// ---------------- fused: causal conv(K=4) + bias + SiLU + headwise qkv ----------------
// Writes fp32 q,k,v (gates) + tf32-exact shadows (attention).
__global__ void conv_head_kernel(const float* __restrict__ conv_k,
                                 const float* __restrict__ conv_b,
                                 const float* __restrict__ Wq,
                                 const float* __restrict__ Wk,
                                 const float* __restrict__ Wv) {
    int idx = blockIdx.x * blockDim.x + threadIdx.x;
    if (idx >= TOT * NPH) return;
    int head = idx % NPH;
    int p = idx / NPH;
    int s = p % Sn;
    int h4 = head * 4;

    float4 bv = *(const float4*)&conv_b[h4];
    float a[4] = {bv.x, bv.y, bv.z, bv.w};
    float xv[4];
    #pragma unroll
    for (int j = 0; j < 4; j++) {
        int t = s - 3 + j;
        if (t >= 0) {
            float4 xm = *(const float4*)&g_xinner[(size_t)(p - s + t) * H2n + h4];
            float4 w  = *(const float4*)&conv_k[j * Hn + h4];
            a[0] += xm.x * w.x; a[1] += xm.y * w.y;
            a[2] += xm.z * w.z; a[3] += xm.w * w.w;
            if (j == 3) { xv[0] = xm.x; xv[1] = xm.y; xv[2] = xm.z; xv[3] = xm.w; }
        }
    }
    #pragma unroll
    for (int u = 0; u < 4; u++) a[u] = a[u] / (1.f + expf(-a[u]));
    *(float4*)&g_act[(size_t)p * Hn + h4] = make_float4(a[0], a[1], a[2], a[3]);

    float q[4] = {0, 0, 0, 0}, k[4] = {0, 0, 0, 0}, v[4] = {0, 0, 0, 0};
    #pragma unroll
    for (int d = 0; d < 4; d++) {
        float4 wq = *(const float4*)&Wq[head * 16 + d * 4];
        float4 wk = *(const float4*)&Wk[head * 16 + d * 4];
        float4 wv = *(const float4*)&Wv[head * 16 + d * 4];
        q[0] += a[d] * wq.x; q[1] += a[d] * wq.y; q[2] += a[d] * wq.z; q[3] += a[d] * wq.w;
        k[0] += a[d] * wk.x; k[1] += a[d] * wk.y; k[2] += a[d] * wk.z; k[3] += a[d] * wk.w;
        v[0] += xv[d] * wv.x; v[1] += xv[d] * wv.y; v[2] += xv[d] * wv.z; v[3] += xv[d] * wv.w;
    }
    size_t o = (size_t)p * Hn + h4;
    *(float4*)&g_q[o] = make_float4(q[0], q[1], q[2], q[3]);
    *(float4*)&g_k[o] = make_float4(k[0], k[1], k[2], k[3]);
    *(float4*)&g_v[o] = make_float4(v[0], v[1], v[2], v[3]);
    *(uint4*)&g_qt[o] = make_uint4(f2tf32(q[0]), f2tf32(q[1]), f2tf32(q[2]), f2tf32(q[3]));
    *(uint4*)&g_kt[o] = make_uint4(f2tf32(k[0]), f2tf32(k[1]), f2tf32(k[2]), f2tf32(k[3]));
    *(uint4*)&g_vt[o] = make_uint4(f2tf32(v[0]), f2tf32(v[1]), f2tf32(v[2]), f2tf32(v[3]));
}

// ---------------- input/forget gate projections ----------------
#define GR 4
__global__ void gates_kernel(const float* __restrict__ W_ig,
                             const float* __restrict__ b_ig,
                             const float* __restrict__ W_fg,
                             const float* __restrict__ b_fg) {
    int p0 = blockIdx.x * GR;
    int tid = threadIdx.x;       // 256
    int lane = tid & 31, warp = tid >> 5;
    float acc[GR][8];
    #pragma unroll
    for (int r = 0; r < GR; r++)
        #pragma unroll
        for (int v = 0; v < 8; v++) acc[r][v] = 0.f;

    const float4* wig4 = (const float4*)W_ig;
    const float4* wfg4 = (const float4*)W_fg;
    for (int i = tid; i < 3 * Hn; i += 256) {
        float4 wi = wig4[i];
        float4 wf = wfg4[i];
        const float* src;
        int off;
        if (i < Hn)          { src = g_q; off = i; }
        else if (i < 2 * Hn) { src = g_k; off = i - Hn; }
        else                 { src = g_v; off = i - 2 * Hn; }
        #pragma unroll
        for (int r = 0; r < GR; r++) {
            float g = src[(size_t)(p0 + r) * Hn + off];
            acc[r][0] += g * wi.x; acc[r][1] += g * wi.y;
            acc[r][2] += g * wi.z; acc[r][3] += g * wi.w;
            acc[r][4] += g * wf.x; acc[r][5] += g * wf.y;
            acc[r][6] += g * wf.z; acc[r][7] += g * wf.w;
        }
    }
    #pragma unroll
    for (int r = 0; r < GR; r++)
        #pragma unroll
        for (int v = 0; v < 8; v++)
            #pragma unroll
            for (int o = 16; o > 0; o >>= 1)
                acc[r][v] += __shfl_down_sync(0xffffffffu, acc[r][v], o);
    __shared__ float sred[8][32];
    if (lane == 0) {
        #pragma unroll
        for (int r = 0; r < GR; r++)
            #pragma unroll
            for (int v = 0; v < 8; v++)
                sred[warp][r * 8 + v] = acc[r][v];
    }
    __syncthreads();
    if (tid < 32) {
        float s = 0.f;
        #pragma unroll
        for (int w = 0; w < 8; w++) s += sred[w][tid];
        int r = tid >> 3, gsel = tid & 7;
        int pp = p0 + r;
        int b = pp / Sn, ss = pp % Sn;
        int n = gsel & 3;
        int o = (b * NHn + n) * Sn + ss;
        if (gsel < 4) {
            g_ig[o] = s + b_ig[n];
        } else {
            float fgv = s + b_fg[n];
            g_lf[o] = fminf(fgv, 0.f) - log1pf(expf(-fabsf(fgv)));
        }
    }
}

// ---------------- parallel scan per (b,n) ----------------
__global__ void scan_kernel() {
    __shared__ float sc[256];
    int bn = blockIdx.x;
    int tid = threadIdx.x;
    int off = bn * Sn + tid * 8;

    float locc[8];
    float run = 0.f;
    #pragma unroll
    for (int j = 0; j < 8; j++) { run += g_lf[off + j]; locc[j] = run; }

    sc[tid] = run;
    __syncthreads();
    for (int d = 1; d < 256; d <<= 1) {
        float add = (tid >= d) ? sc[tid - d] : 0.f;
        __syncthreads();
        sc[tid] += add;
        __syncthreads();
    }
    float coff = sc[tid] - run;

    float av[8];
    float rmax = -INFINITY;
    #pragma unroll
    for (int j = 0; j < 8; j++) {
        locc[j] += coff;
        av[j] = g_ig[off + j] - locc[j];
        rmax = fmaxf(rmax, av[j]);
    }
    __syncthreads();

    sc[tid] = rmax;
    __syncthreads();
    for (int d = 1; d < 256; d <<= 1) {
        float m = (tid >= d) ? sc[tid - d] : -INFINITY;
        __syncthreads();
        sc[tid] = fmaxf(sc[tid], m);
        __syncthreads();
    }
    float Mr = (tid == 0) ? -INFINITY : sc[tid - 1];

    #pragma unroll
    for (int j = 0; j < 8; j++) {
        Mr = fmaxf(Mr, av[j]);
        g_a[off + j] = av[j];
        g_M[off + j] = Mr;
        g_nfl[off + j] = expf(-(locc[j] + Mr));
    }
}

// ---------------- tensor-core tiled mLSTM cell (cp.async staging + ldmatrix) ----------------
// grid: (NQT, B*NH), 256 threads = 8 warps (wm=warp>>1: 4 m16-rows; wn=warp&1: n halves).
__global__ __launch_bounds__(256) void attn_mma_kernel() {
    extern __shared__ uint32_t us[];
    uint32_t* sQ  = us + USM_Q;    // [64][SKS] tf32
    uint32_t* sKV = us + USM_KV;   // [64][SKS] tf32 (K then V per k-tile)
    uint32_t* sW  = us + USM_W;    // [64][WS]  tf32 weights
    float* sM   = (float*)(us + USM_M);
    float* sA   = (float*)(us + USM_A);
    float* sSum = (float*)(us + USM_SUM);

    int bn = blockIdx.y;
    int n = bn % NHn, b = bn / NHn;
    int qt = (NQT - 1) - blockIdx.x;   // longest blocks first
    int q0 = qt * TQ;
    int tid = threadIdx.x;
    int lane = tid & 31, warp = tid >> 5;
    int wm = warp >> 1, wn = warp & 1;
    int abase = bn * Sn;

    // stage Q via cp.async (pre-rounded tf32 shadow)
    #pragma unroll 3
    for (int i = tid; i < TQ * DH4; i += 256) {
        int r = i / DH4, c = i % DH4;
        cp16(smem_u32(&sQ[r * SKS + 4 * c]),
             &g_qt[(size_t)(b * Sn + q0 + r) * Hn + n * DHn + 4 * c]);
    }
    cp_commit();
    if (tid < TQ) {
        sM[tid] = g_M[abase + q0 + tid];
        sSum[tid] = 0.f;
    }
    cp_wait0();
    __syncthreads();

    int r0 = wm * 16 + (lane >> 2);       // this thread's first C row
    float Ms0 = sM[r0], Ms1 = sM[r0 + 8];
    const float scale = rsqrtf((float)DHn);

    // ldmatrix addressing
    int jj = lane & 7, sel = lane >> 3;
    uint32_t qbase = smem_u32(&sQ[(wm * 16 + (sel & 1) * 8 + jj) * SKS + (sel >> 1) * 4]);
    uint32_t kbase = smem_u32(&sKV[(wn * 32 + sel * 8 + jj) * SKS]);
    uint32_t wbase = smem_u32(&sW[(wm * 16 + (sel & 1) * 8 + jj) * WS + (sel >> 1) * 4]);

    // PV accumulators: rows {r0, r0+8}, cols wn*168 + nt*8 + 2*(lane&3) (+1)
    float acc[21][4];
    #pragma unroll
    for (int nt = 0; nt < 21; nt++)
        #pragma unroll
        for (int e = 0; e < 4; e++) acc[nt][e] = 0.f;

    int nkt = qt + 1;
    for (int kt = 0; kt < nkt; kt++) {
        int k0 = kt * TK;
        __syncthreads();   // prior PV finished with sKV/sW
        // stage K via cp.async
        #pragma unroll 3
        for (int i = tid; i < TK * DH4; i += 256) {
            int r = i / DH4, c = i % DH4;
            cp16(smem_u32(&sKV[r * SKS + 4 * c]),
                 &g_kt[(size_t)(b * Sn + k0 + r) * Hn + n * DHn + 4 * c]);
        }
        cp_commit();
        if (tid < TK) sA[tid] = g_a[abase + k0 + tid];
        cp_wait0();
        __syncthreads();

        // ---- QK^T: warp computes rows [wm*16, +16), keys [wn*32, +32) ----
        float wacc[4][4];
        #pragma unroll
        for (int nt = 0; nt < 4; nt++)
            #pragma unroll
            for (int e = 0; e < 4; e++) wacc[nt][e] = 0.f;

        #pragma unroll 2
        for (int c8 = 0; c8 < 42; c8++) {
            uint32_t af[4], bf0[4], bf1[4];
            ldsm_x4(af,  qbase + (uint32_t)c8 * 32u);
            ldsm_x4(bf0, kbase + (uint32_t)c8 * 32u);
            ldsm_x4(bf1, kbase + (uint32_t)c8 * 32u + 16u);
            #pragma unroll
            for (int nt = 0; nt < 4; nt++) {
                uint32_t b2[2] = {bf0[nt], bf1[nt]};
                mma_tf32(wacc[nt], af, b2);
            }
        }

        // ---- postprocess: mask, scale*exp, tf32-round to sW, row sums ----
        float rs0 = 0.f, rs1 = 0.f;
        #pragma unroll
        for (int nt = 0; nt < 4; nt++) {
            int c0 = wn * 32 + nt * 8 + 2 * (lane & 3);
            int t0 = k0 + c0;
            float ea0 = sA[c0], ea1 = sA[c0 + 1];
            float w00 = (t0     <= q0 + r0)     ? wacc[nt][0] * scale * __expf(ea0 - Ms0) : 0.f;
            float w01 = (t0 + 1 <= q0 + r0)     ? wacc[nt][1] * scale * __expf(ea1 - Ms0) : 0.f;
            float w10 = (t0     <= q0 + r0 + 8) ? wacc[nt][2] * scale * __expf(ea0 - Ms1) : 0.f;
            float w11 = (t0 + 1 <= q0 + r0 + 8) ? wacc[nt][3] * scale * __expf(ea1 - Ms1) : 0.f;
            uint32_t u00 = f2tf32(w00), u01 = f2tf32(w01);
            uint32_t u10 = f2tf32(w10), u11 = f2tf32(w11);
            sW[r0 * WS + c0]           = u00;
            sW[r0 * WS + c0 + 1]       = u01;
            sW[(r0 + 8) * WS + c0]     = u10;
            sW[(r0 + 8) * WS + c0 + 1] = u11;
            rs0 += __uint_as_float(u00) + __uint_as_float(u01);
            rs1 += __uint_as_float(u10) + __uint_as_float(u11);
        }
        rs0 += __shfl_xor_sync(0xffffffffu, rs0, 1);
        rs0 += __shfl_xor_sync(0xffffffffu, rs0, 2);
        rs1 += __shfl_xor_sync(0xffffffffu, rs1, 1);
        rs1 += __shfl_xor_sync(0xffffffffu, rs1, 2);
        if ((lane & 3) == 0) {
            atomicAdd(&sSum[r0], rs0);
            atomicAdd(&sSum[r0 + 8], rs1);
        }
        __syncthreads();   // sW complete; sKV free

        // stage V via cp.async
        #pragma unroll 3
        for (int i = tid; i < TK * DH4; i += 256) {
            int r = i / DH4, c = i % DH4;
            cp16(smem_u32(&sKV[r * SKS + 4 * c]),
                 &g_vt[(size_t)(b * Sn + k0 + r) * Hn + n * DHn + 4 * c]);
        }
        cp_commit();
        cp_wait0();
        __syncthreads();

        // ---- PV: warp computes rows [wm*16, +16), dims [wn*168, +168) ----
        #pragma unroll
        for (int k8 = 0; k8 < 8; k8++) {
            uint32_t af[4];
            ldsm_x4(af, wbase + (uint32_t)k8 * 32u);
            int tb = k8 * 8 + (lane & 3);
            #pragma unroll
            for (int nt = 0; nt < 21; nt++) {
                int d = wn * 168 + nt * 8 + (lane >> 2);
                uint32_t bf[2];
                bf[0] = sKV[tb * SKS + d];
                bf[1] = sKV[(tb + 4) * SKS + d];
                mma_tf32(acc[nt], af, bf);
            }
        }
    }
    __syncthreads();

    // ---- epilogue: normalize and store ----
    float s0 = sSum[r0], s1 = sSum[r0 + 8];
    float inv0 = 1.f / (fmaxf(fabsf(s0), g_nfl[abase + q0 + r0]) + 1e-6f);
    float inv1 = 1.f / (fmaxf(fabsf(s1), g_nfl[abase + q0 + r0 + 8]) + 1e-6f);
    float* orow0 = &g_h[(size_t)(b * Sn + q0 + r0) * Hn + n * DHn];
    float* orow1 = &g_h[(size_t)(b * Sn + q0 + r0 + 8) * Hn + n * DHn];
    #pragma unroll
    for (int nt = 0; nt < 21; nt++) {
        int d = wn * 168 + nt * 8 + 2 * (lane & 3);
        *(float2*)&orow0[d] = make_float2(acc[nt][0] * inv0, acc[nt][1] * inv0);
        *(float2*)&orow1[d] = make_float2(acc[nt][2] * inv1, acc[nt][3] * inv1);
    }
}

// ---------------- per-head LN + skip + SiLU(z) gate ----------------
__global__ void ln_gate_kernel(const float* __restrict__ ln_w,
                               const float* __restrict__ skip) {
    int rid = blockIdx.x;
    int p = rid >> 2;
    int n = rid & 3;
    int tid = threadIdx.x;         // 128
    const float* hrow = &g_h[(size_t)p * Hn + n * DHn];

    float sum = 0.f, sq = 0.f;
    for (int d = tid; d < DHn; d += 128) {
        float v = hrow[d];
        sum += v; sq += v * v;
    }
    __shared__ float s1[4], s2[4], sbc[2];
    #pragma unroll
    for (int o = 16; o > 0; o >>= 1) {
        sum += __shfl_down_sync(0xffffffffu, sum, o);
        sq  += __shfl_down_sync(0xffffffffu, sq, o);
    }
    if ((tid & 31) == 0) { s1[tid >> 5] = sum; s2[tid >> 5] = sq; }
    __syncthreads();
    if (tid == 0) {
        float ts = s1[0] + s1[1] + s1[2] + s1[3];
        float tq = s2[0] + s2[1] + s2[2] + s2[3];
        float mu = ts / (float)DHn;
        float var = fmaxf(tq / (float)DHn - mu * mu, 0.f);
        sbc[0] = mu;
        sbc[1] = rsqrtf(var + 1e-5f);
    }
    __syncthreads();
    float mu = sbc[0], rs = sbc[1];
    for (int d = tid; d < DHn; d += 128) {
        int hidx = n * DHn + d;
        float hnv = (hrow[d] - mu) * rs * ln_w[hidx];
        float z = g_xinner[(size_t)p * H2n + Hn + hidx];
        float sz = z / (1.f + expf(-z));
        g_hst[(size_t)p * Hn + hidx] = (hnv + skip[hidx] * g_act[(size_t)p * Hn + hidx]) * sz;
    }
}

// ---------------- launch ----------------
extern "C" void kernel_launch(void* const* d_in, const int* in_sizes, int n_in,
                              void* d_out, int out_size) {
    const float* x      = (const float*)d_in[0];
    const float* W_up   = (const float*)d_in[1];
    const float* conv_k = (const float*)d_in[2];
    const float* conv_b = (const float*)d_in[3];
    const float* Wq     = (const float*)d_in[4];
    const float* Wk     = (const float*)d_in[5];
    const float* Wv     = (const float*)d_in[6];
    const float* W_ig   = (const float*)d_in[7];
    const float* b_ig   = (const float*)d_in[8];
    const float* W_fg   = (const float*)d_in[9];
    const float* b_fg   = (const float*)d_in[10];
    const float* ln_w   = (const float*)d_in[11];
    const float* skip   = (const float*)d_in[12];
    const float* W_down = (const float*)d_in[13];
    float* out = (float*)d_out;

    void *p_xinner = nullptr, *p_hst = nullptr;
    cudaGetSymbolAddress(&p_xinner, g_xinner);
    cudaGetSymbolAddress(&p_hst, g_hst);

    static bool attr_set = false;
    if (!attr_set) {
        cudaFuncSetAttribute(attn_mma_kernel,
                             cudaFuncAttributeMaxDynamicSharedMemorySize,
                             ATTN_SMEM_BYTES);
        attr_set = true;
    }

    // 1. up projection: (4096x1024) @ (1024x2688) — tf32 tensor cores
    mma_gemm_kernel<<<dim3(H2n / 128, TOT / 128), 256>>>(x, W_up, (float*)p_xinner,
                                                         TOT, H2n, En);
    // 2. fused conv + SiLU + headwise qkv (+ tf32 shadows)
    {
        int nthr = TOT * NPH;
        conv_head_kernel<<<(nthr + 255) / 256, 256>>>(conv_k, conv_b, Wq, Wk, Wv);
    }
    // 3. gate projections
    gates_kernel<<<TOT / GR, 256>>>(W_ig, b_ig, W_fg, b_fg);
    // 4. per-(b,n) parallel scan
    scan_kernel<<<Bn * NHn, 256>>>();
    // 5. tensor-core tiled mLSTM cell (cp.async + ldmatrix)
    attn_mma_kernel<<<dim3(NQT, Bn * NHn), 256, ATTN_SMEM_BYTES>>>();
    // 6. multi-head LN + skip + SiLU(z) gate
    ln_gate_kernel<<<TOT * NHn, 128>>>(ln_w, skip);
    // 7. down projection: (4096x1344) @ (1344x1024) — tf32 tensor cores
    mma_gemm_kernel<<<dim3(En / 128, TOT / 128), 256>>>((const float*)p_hst, W_down,
                                                        out, TOT, En, Hn);
}